// round 9
// baseline (speedup 1.0000x reference)
#include <cuda_runtime.h>

// Problem shape (fixed by the dataset)
#define BB 64
#define LL 4096
#define EE 256
#define HH 256
#define SPLITS 9             // 64*9 = 576 CTAs = one wave at 4 CTAs/SM
#define NW 8                 // warps per CTA in k1
#define TILE 16              // rows per TMA tile (16 KB)
#define NSTAGES 2            // smem ring stages

// Scratch (no allocations allowed in kernel_launch)
__device__ float g_Wh[BB * EE];
__device__ float g_pm[BB * SPLITS];
__device__ float g_pd[BB * SPLITS];
__device__ float g_pctx[BB * SPLITS * EE];
__device__ int   g_cnt[BB];

// ---------------- PTX helpers ----------------
__device__ __forceinline__ unsigned smem_u32(const void* p) {
    return (unsigned)__cvta_generic_to_shared(p);
}
__device__ __forceinline__ void mbar_init(unsigned mb, unsigned cnt) {
    asm volatile("mbarrier.init.shared.b64 [%0], %1;" :: "r"(mb), "r"(cnt) : "memory");
}
__device__ __forceinline__ void mbar_expect_tx(unsigned mb, unsigned bytes) {
    asm volatile("mbarrier.arrive.expect_tx.shared.b64 _, [%0], %1;"
                 :: "r"(mb), "r"(bytes) : "memory");
}
__device__ __forceinline__ void tma_bulk_1d(unsigned dst, const void* src,
                                            unsigned bytes, unsigned mb) {
    asm volatile(
        "cp.async.bulk.shared::cta.global.mbarrier::complete_tx::bytes "
        "[%0], [%1], %2, [%3];"
        :: "r"(dst), "l"(src), "r"(bytes), "r"(mb) : "memory");
}
__device__ __forceinline__ void mbar_wait(unsigned mb, unsigned parity) {
    asm volatile(
        "{\n\t"
        ".reg .pred P;\n\t"
        "LWAIT%=:\n\t"
        "mbarrier.try_wait.parity.acquire.cta.shared::cta.b64 P, [%0], %1, 0x989680;\n\t"
        "@P bra LDONE%=;\n\t"
        "bra LWAIT%=;\n\t"
        "LDONE%=:\n\t"
        "}"
        :: "r"(mb), "r"(parity) : "memory");
}

// -------------------------------------------------------------------------
// k0: Wh[b,e] = sum_h W[e,h] * hidden[b,h]. One warp per 4 e's (4 ILP
// shuffle chains). Also zeroes the per-batch completion counters.
// grid = (EE/(NW*4), BB) = (8, 64), block = 256.
// -------------------------------------------------------------------------
__global__ __launch_bounds__(256) void k0_wh(const float* __restrict__ W,
                                             const float* __restrict__ hidden) {
    const int b = blockIdx.y;
    const int t = threadIdx.x;
    const int w = t >> 5;
    const int lane = t & 31;

    if (blockIdx.x == 0 && t == 0) g_cnt[b] = 0;

    const int e0 = (blockIdx.x * NW + w) * 4;
    const float4* hv = reinterpret_cast<const float4*>(hidden + (size_t)b * HH);
    const float4 h0 = __ldg(hv + lane);
    const float4 h1 = __ldg(hv + lane + 32);

    float p[4];
#pragma unroll
    for (int i = 0; i < 4; i++) {
        const float4* Wr = reinterpret_cast<const float4*>(W + (size_t)(e0 + i) * HH);
        const float4 w0 = __ldg(Wr + lane);
        const float4 w1 = __ldg(Wr + lane + 32);
        p[i] = w0.x * h0.x + w0.y * h0.y + w0.z * h0.z + w0.w * h0.w
             + w1.x * h1.x + w1.y * h1.y + w1.z * h1.z + w1.w * h1.w;
    }
#pragma unroll
    for (int s = 16; s >= 1; s >>= 1) {
#pragma unroll
        for (int i = 0; i < 4; i++)
            p[i] += __shfl_xor_sync(0xffffffffu, p[i], s);
    }
    if (lane < 4) g_Wh[b * EE + e0 + lane] = p[lane];
}

// -------------------------------------------------------------------------
// k1: single pass over enc via 1D bulk-TMA double-buffered smem ring,
// fused split-combine. One CTA = (split s, batch b), 8 warps, single wave.
// Per tile (16 rows), warp w consumes rows w and w+8 (two interleaved
// shuffle chains). Online softmax with rescale-on-new-max.
// Last CTA per batch combines splits, writes out, resets the counter.
// -------------------------------------------------------------------------
__global__ __launch_bounds__(256, 4) void k1_pass(const float* __restrict__ enc,
                                                  float* __restrict__ out) {
    const int s = blockIdx.x;
    const int b = blockIdx.y;
    const int t = threadIdx.x;
    const int w = t >> 5;
    const int lane = t & 31;

    __shared__ float4 buf[NSTAGES][TILE * (EE / 4)];   // 32 KB ring
    __shared__ float4 wh_s[EE / 4];
    __shared__ float sm_m[NW];
    __shared__ float sm_d[NW];
    __shared__ float sm_ctx[NW][EE];
    __shared__ __align__(8) unsigned long long mbar[NSTAGES];
    __shared__ int s_last;

    const unsigned mb0 = smem_u32(&mbar[0]);

    if (t < EE / 4)
        wh_s[t] = reinterpret_cast<const float4*>(g_Wh + b * EE)[t];
    if (t == 0) {
#pragma unroll
        for (int i = 0; i < NSTAGES; i++) mbar_init(mb0 + 8u * i, 1u);
    }
    __syncthreads();

    const int begin = (s * LL) / SPLITS;
    const int end   = ((s + 1) * LL) / SPLITS;
    const int rows  = end - begin;
    const int ntiles = (rows + TILE - 1) / TILE;

    const char* gsrc = reinterpret_cast<const char*>(enc)
                     + ((size_t)b * LL + begin) * (EE * 4);

    // prefill the ring
    if (t == 0) {
#pragma unroll
        for (int i = 0; i < NSTAGES; i++) {
            if (i < ntiles) {
                const int rcnt = min(TILE, rows - i * TILE);
                const unsigned bytes = (unsigned)rcnt * (EE * 4);
                mbar_expect_tx(mb0 + 8u * i, bytes);
                tma_bulk_1d(smem_u32(&buf[i][0]), gsrc + (size_t)i * TILE * EE * 4,
                            bytes, mb0 + 8u * i);
            }
        }
    }

    const float4 wh0 = wh_s[lane];
    const float4 wh1 = wh_s[lane + 32];

    float m = -1e30f, d = 0.f;
    float4 c0 = make_float4(0.f, 0.f, 0.f, 0.f);
    float4 c1 = make_float4(0.f, 0.f, 0.f, 0.f);

    for (int tl = 0; tl < ntiles; tl++) {
        const int st = tl % NSTAGES;
        const unsigned par = (unsigned)((tl / NSTAGES) & 1);
        mbar_wait(mb0 + 8u * st, par);

        const int rcnt = min(TILE, rows - tl * TILE);
        const bool hA = w < rcnt;
        const bool hB = w + 8 < rcnt;
        const float4* base = &buf[st][0];

        float4 a0, a1, b0, b1;
        if (hA) {
            a0 = base[w * (EE / 4) + lane];
            a1 = base[w * (EE / 4) + lane + 32];
        }
        if (hB) {
            b0 = base[(w + 8) * (EE / 4) + lane];
            b1 = base[(w + 8) * (EE / 4) + lane + 32];
        }

        float pA = 0.f, pB = 0.f;
        if (hA)
            pA = a0.x * wh0.x + a0.y * wh0.y + a0.z * wh0.z + a0.w * wh0.w
               + a1.x * wh1.x + a1.y * wh1.y + a1.z * wh1.z + a1.w * wh1.w;
        if (hB)
            pB = b0.x * wh0.x + b0.y * wh0.y + b0.z * wh0.z + b0.w * wh0.w
               + b1.x * wh1.x + b1.y * wh1.y + b1.z * wh1.z + b1.w * wh1.w;

        pA += __shfl_xor_sync(0xffffffffu, pA, 16);
        pB += __shfl_xor_sync(0xffffffffu, pB, 16);
        pA += __shfl_xor_sync(0xffffffffu, pA, 8);
        pB += __shfl_xor_sync(0xffffffffu, pB, 8);
        pA += __shfl_xor_sync(0xffffffffu, pA, 4);
        pB += __shfl_xor_sync(0xffffffffu, pB, 4);
        pA += __shfl_xor_sync(0xffffffffu, pA, 2);
        pB += __shfl_xor_sync(0xffffffffu, pB, 2);
        pA += __shfl_xor_sync(0xffffffffu, pA, 1);
        pB += __shfl_xor_sync(0xffffffffu, pB, 1);

        if (hA) {
            if (pA > m) {
                const float sc = __expf(m - pA);
                d *= sc;
                c0.x *= sc; c0.y *= sc; c0.z *= sc; c0.w *= sc;
                c1.x *= sc; c1.y *= sc; c1.z *= sc; c1.w *= sc;
                m = pA;
            }
            const float e = __expf(pA - m);
            d += e;
            c0.x += e * a0.x; c0.y += e * a0.y; c0.z += e * a0.z; c0.w += e * a0.w;
            c1.x += e * a1.x; c1.y += e * a1.y; c1.z += e * a1.z; c1.w += e * a1.w;
        }
        if (hB) {
            if (pB > m) {
                const float sc = __expf(m - pB);
                d *= sc;
                c0.x *= sc; c0.y *= sc; c0.z *= sc; c0.w *= sc;
                c1.x *= sc; c1.y *= sc; c1.z *= sc; c1.w *= sc;
                m = pB;
            }
            const float e = __expf(pB - m);
            d += e;
            c0.x += e * b0.x; c0.y += e * b0.y; c0.z += e * b0.z; c0.w += e * b0.w;
            c1.x += e * b1.x; c1.y += e * b1.y; c1.z += e * b1.z; c1.w += e * b1.w;
        }

        __syncthreads();   // all warps done with this stage's smem

        // refill this stage with tile tl + NSTAGES
        const int ntl = tl + NSTAGES;
        if (t == 0 && ntl < ntiles) {
            const int nr = min(TILE, rows - ntl * TILE);
            const unsigned bytes = (unsigned)nr * (EE * 4);
            mbar_expect_tx(mb0 + 8u * st, bytes);
            tma_bulk_1d(smem_u32(&buf[st][0]),
                        gsrc + (size_t)ntl * TILE * EE * 4, bytes, mb0 + 8u * st);
        }
    }

    // CTA-level combine
    if (lane == 0) { sm_m[w] = m; sm_d[w] = d; }
    __syncthreads();

    float M = sm_m[0];
#pragma unroll
    for (int i = 1; i < NW; i++) M = fmaxf(M, sm_m[i]);
    float D = 0.f;
#pragma unroll
    for (int i = 0; i < NW; i++) D += sm_d[i] * __expf(sm_m[i] - M);

    const float sc = __expf(m - M);   // m is warp-uniform after butterfly
    sm_ctx[w][lane * 4 + 0] = c0.x * sc;
    sm_ctx[w][lane * 4 + 1] = c0.y * sc;
    sm_ctx[w][lane * 4 + 2] = c0.z * sc;
    sm_ctx[w][lane * 4 + 3] = c0.w * sc;
    sm_ctx[w][128 + lane * 4 + 0] = c1.x * sc;
    sm_ctx[w][128 + lane * 4 + 1] = c1.y * sc;
    sm_ctx[w][128 + lane * 4 + 2] = c1.z * sc;
    sm_ctx[w][128 + lane * 4 + 3] = c1.w * sc;
    __syncthreads();

    float acc = 0.f;
#pragma unroll
    for (int i = 0; i < NW; i++) acc += sm_ctx[i][t];

    const int idx = b * SPLITS + s;
    g_pctx[(size_t)idx * EE + t] = acc;
    if (t == 0) { g_pm[idx] = M; g_pd[idx] = D; }

    // ---- fused split-combine: last CTA of this batch finishes the output ----
    __threadfence();
    if (t == 0) {
        const int old = atomicAdd(&g_cnt[b], 1);
        s_last = (old == SPLITS - 1);
    }
    __syncthreads();
    if (!s_last) return;
    __threadfence();   // acquire: make other CTAs' partials visible

    float pm[SPLITS];
#pragma unroll
    for (int i = 0; i < SPLITS; i++) pm[i] = g_pm[b * SPLITS + i];
    float Mg = pm[0];
#pragma unroll
    for (int i = 1; i < SPLITS; i++) Mg = fmaxf(Mg, pm[i]);
    float Dg = 0.f;
#pragma unroll
    for (int i = 0; i < SPLITS; i++) Dg += g_pd[b * SPLITS + i] * __expf(pm[i] - Mg);

    float accg = 0.f;
#pragma unroll
    for (int i = 0; i < SPLITS; i++)
        accg += g_pctx[(size_t)(b * SPLITS + i) * EE + t] * __expf(pm[i] - Mg);

    out[b * EE + t] = accg / Dg;

    if (t == 0) g_cnt[b] = 0;   // clean state for next graph replay
}

// -------------------------------------------------------------------------
// Inputs (metadata order): hidden [B,H] f32, encoderhidden [B,L,E] f32,
// W [E,H] f32, b [1] f32 (softmax-invariant -> ignored).
// Output: context [B,E] f32.
// -------------------------------------------------------------------------
extern "C" void kernel_launch(void* const* d_in, const int* in_sizes, int n_in,
                              void* d_out, int out_size) {
    const float* hidden = (const float*)d_in[0];
    const float* enc    = (const float*)d_in[1];
    const float* W      = (const float*)d_in[2];
    float* out          = (float*)d_out;

    k0_wh<<<dim3(EE / (NW * 4), BB), 256>>>(W, hidden);
    k1_pass<<<dim3(SPLITS, BB), 256>>>(enc, out);
}